// round 1
// baseline (speedup 1.0000x reference)
#include <cuda_runtime.h>

// ---------------- scratch (static device globals; no allocation) ------------
#define N_MAX 100096
__device__ float g_agg[(size_t)100000 * 128];
__device__ float g_t  [(size_t)100000 * 128];
__device__ float g_h  [(size_t)100000 * 128];
__device__ float g_pool[1024 * 128];
__device__ int   g_idx64;   // 1 if indices are int64, 0 if int32

// ---------------- index dtype detection -------------------------------------
// int64 node ids < 2^31 => every odd 32-bit word is 0. For int32 data the odd
// words are random node ids (almost surely nonzero somewhere in 256 samples).
__global__ void detect_kernel(const unsigned int* __restrict__ w, long long n32) {
    long long nelem = n32 / 2;            // candidate int64 element count
    int is64 = 1;
    for (int i = 0; i < 256; i++) {
        long long e = (i * (nelem - 1)) / 255;
        if (w[2 * e + 1] != 0u) { is64 = 0; break; }
    }
    g_idx64 = is64;
}

__device__ __forceinline__ int load_idx(const void* p, long long i) {
    if (g_idx64) return (int)((const long long*)p)[i];
    return ((const int*)p)[i];
}

// ---------------- zero -------------------------------------------------------
__global__ void zero_kernel(float* __restrict__ p, int n4) {
    int i = blockIdx.x * blockDim.x + threadIdx.x;
    if (i < n4) reinterpret_cast<float4*>(p)[i] = make_float4(0.f, 0.f, 0.f, 0.f);
}

// ---------------- edge scatter-add: agg[dst] += h[src] -----------------------
__global__ void scatter_kernel(const float* __restrict__ h, const void* __restrict__ ei,
                               int E, float* __restrict__ agg) {
    int w = (blockIdx.x * blockDim.x + threadIdx.x) >> 5;
    int lane = threadIdx.x & 31;
    if (w >= E) return;
    int src = load_idx(ei, w);
    int dst = load_idx(ei, (long long)E + w);
    const float4 v = *reinterpret_cast<const float4*>(h + (size_t)src * 128 + lane * 4);
    float* o = agg + (size_t)dst * 128 + lane * 4;
    atomicAdd(o + 0, v.x);
    atomicAdd(o + 1, v.y);
    atomicAdd(o + 2, v.z);
    atomicAdd(o + 3, v.w);
}

// ---------------- fused GEMM: C = relu((A [+ A2]) @ W + bias) ---------------
// A: [M,128] row-major, W: [128,128] row-major (k-major rows), C: [M,128].
// Block tile 128x128, thread tile 8x8 (split 4+4 to avoid smem conflicts).
template <bool ADD>
__global__ __launch_bounds__(256, 2)
void gemm_relu_kernel(const float* __restrict__ A, const float* __restrict__ A2,
                      const float* __restrict__ W, const float* __restrict__ bias,
                      float* __restrict__ C, int M) {
    __shared__ float As[16][128];
    __shared__ float Bs[16][128];

    const int tid  = threadIdx.x;
    const int row0 = blockIdx.x * 128;
    const int ty = tid >> 4;          // 0..15
    const int tx = tid & 15;          // 0..15

    // loader mapping
    const int lr   = tid >> 1;        // 0..127 : tile row
    const int lseg = (tid & 1) * 8;   // 0 or 8 : k offset
    const int bk   = tid >> 4;        // 0..15  : k row for W
    const int bn   = (tid & 15) * 8;  // 0..120 : col

    float acc[8][8];
#pragma unroll
    for (int i = 0; i < 8; i++)
#pragma unroll
        for (int j = 0; j < 8; j++) acc[i][j] = 0.f;

    const int  grow = row0 + lr;
    const bool rok  = grow < M;
    const float* Ap  = A  + (size_t)grow * 128;
    const float* A2p = ADD ? (A2 + (size_t)grow * 128) : A;

    for (int kt = 0; kt < 128; kt += 16) {
        float4 a0, a1;
        if (rok) {
            a0 = *reinterpret_cast<const float4*>(Ap + kt + lseg);
            a1 = *reinterpret_cast<const float4*>(Ap + kt + lseg + 4);
            if (ADD) {
                float4 c0 = *reinterpret_cast<const float4*>(A2p + kt + lseg);
                float4 c1 = *reinterpret_cast<const float4*>(A2p + kt + lseg + 4);
                a0.x += c0.x; a0.y += c0.y; a0.z += c0.z; a0.w += c0.w;
                a1.x += c1.x; a1.y += c1.y; a1.z += c1.z; a1.w += c1.w;
            }
        } else {
            a0 = make_float4(0.f, 0.f, 0.f, 0.f); a1 = a0;
        }
        As[lseg + 0][lr] = a0.x; As[lseg + 1][lr] = a0.y;
        As[lseg + 2][lr] = a0.z; As[lseg + 3][lr] = a0.w;
        As[lseg + 4][lr] = a1.x; As[lseg + 5][lr] = a1.y;
        As[lseg + 6][lr] = a1.z; As[lseg + 7][lr] = a1.w;

        *reinterpret_cast<float4*>(&Bs[bk][bn]) =
            *reinterpret_cast<const float4*>(W + (size_t)(kt + bk) * 128 + bn);
        *reinterpret_cast<float4*>(&Bs[bk][bn + 4]) =
            *reinterpret_cast<const float4*>(W + (size_t)(kt + bk) * 128 + bn + 4);

        __syncthreads();
#pragma unroll
        for (int kk = 0; kk < 16; kk++) {
            float a[8], b[8];
            *reinterpret_cast<float4*>(a)     = *reinterpret_cast<float4*>(&As[kk][ty * 4]);
            *reinterpret_cast<float4*>(a + 4) = *reinterpret_cast<float4*>(&As[kk][ty * 4 + 64]);
            *reinterpret_cast<float4*>(b)     = *reinterpret_cast<float4*>(&Bs[kk][tx * 4]);
            *reinterpret_cast<float4*>(b + 4) = *reinterpret_cast<float4*>(&Bs[kk][tx * 4 + 64]);
#pragma unroll
            for (int i = 0; i < 8; i++)
#pragma unroll
                for (int j = 0; j < 8; j++) acc[i][j] += a[i] * b[j];
        }
        __syncthreads();
    }

#pragma unroll
    for (int i = 0; i < 8; i++) {
        int r = row0 + ty * 4 + (i >> 2) * 64 + (i & 3);
        if (r < M) {
#pragma unroll
            for (int jj = 0; jj < 2; jj++) {
                int c = tx * 4 + jj * 64;
                float4 o;
                o.x = fmaxf(acc[i][jj * 4 + 0] + bias[c + 0], 0.f);
                o.y = fmaxf(acc[i][jj * 4 + 1] + bias[c + 1], 0.f);
                o.z = fmaxf(acc[i][jj * 4 + 2] + bias[c + 2], 0.f);
                o.w = fmaxf(acc[i][jj * 4 + 3] + bias[c + 3], 0.f);
                *reinterpret_cast<float4*>(C + (size_t)r * 128 + c) = o;
            }
        }
    }
}

// ---------------- graph pooling: g[batch[n]] += h[n] -------------------------
__global__ void pool_kernel(const float* __restrict__ h, const void* __restrict__ batch,
                            int N, float* __restrict__ g) {
    int idx = blockIdx.x * blockDim.x + threadIdx.x;
    int node = idx >> 5;
    if (node >= N) return;
    int q = (idx & 31) * 4;
    float4 v = *reinterpret_cast<const float4*>(h + (size_t)node * 128 + q);
    int b = load_idx(batch, node);
    float* o = g + (size_t)b * 128 + q;
    atomicAdd(o + 0, v.x);
    atomicAdd(o + 1, v.y);
    atomicAdd(o + 2, v.z);
    atomicAdd(o + 3, v.w);
}

// ---------------- classifier head + log_softmax ------------------------------
__global__ void head_kernel(const float* __restrict__ gpool,
                            const float* __restrict__ Wl1, const float* __restrict__ bl1,
                            const float* __restrict__ Wl2, const float* __restrict__ bl2,
                            float* __restrict__ out) {
    __shared__ float row[128];
    __shared__ float hid[128];
    __shared__ float lg[10];
    __shared__ float red[2];
    int gi = blockIdx.x;
    int t = threadIdx.x;

    row[t] = gpool[(size_t)gi * 128 + t];
    __syncthreads();

    float s = bl1[t];
#pragma unroll 8
    for (int k = 0; k < 128; k++) s += row[k] * Wl1[k * 128 + t];
    hid[t] = fmaxf(s, 0.f);
    __syncthreads();

    if (t < 10) {
        float v = bl2[t];
#pragma unroll 8
        for (int k = 0; k < 128; k++) v += hid[k] * Wl2[k * 10 + t];
        lg[t] = v;
    }
    __syncthreads();

    if (t == 0) {
        float m = lg[0];
        for (int i = 1; i < 10; i++) m = fmaxf(m, lg[i]);
        float se = 0.f;
        for (int i = 0; i < 10; i++) se += expf(lg[i] - m);
        red[0] = m;
        red[1] = logf(se);
    }
    __syncthreads();

    if (t < 10) out[(size_t)gi * 10 + t] = lg[t] - red[0] - red[1];
}

// ---------------- launch ------------------------------------------------------
extern "C" void kernel_launch(void* const* d_in, const int* in_sizes, int n_in,
                              void* d_out, int out_size) {
    const float* x     = (const float*)d_in[0];
    const void*  ei    = d_in[1];
    const void*  batch = d_in[2];
    const float* W1a = (const float*)d_in[3];
    const float* b1a = (const float*)d_in[4];
    const float* W1b = (const float*)d_in[5];
    const float* b1b = (const float*)d_in[6];
    const float* W2a = (const float*)d_in[7];
    const float* b2a = (const float*)d_in[8];
    const float* W2b = (const float*)d_in[9];
    const float* b2b = (const float*)d_in[10];
    const float* Wl1 = (const float*)d_in[11];
    const float* bl1 = (const float*)d_in[12];
    const float* Wl2 = (const float*)d_in[13];
    const float* bl2 = (const float*)d_in[14];
    float* out = (float*)d_out;

    const int N = in_sizes[0] / 128;
    const int E = in_sizes[1] / 2;

    float *agg, *tb, *hb, *gp;
    cudaGetSymbolAddress((void**)&agg, g_agg);
    cudaGetSymbolAddress((void**)&tb,  g_t);
    cudaGetSymbolAddress((void**)&hb,  g_h);
    cudaGetSymbolAddress((void**)&gp,  g_pool);

    const int zeroN4    = N * 32;                 // N*128/4
    const int zeroBlks  = (zeroN4 + 255) / 256;
    const int scatBlks  = (E + 7) / 8;            // one warp per edge
    const int gemmBlks  = (N + 127) / 128;
    const int poolBlks  = (N * 32 + 255) / 256;

    detect_kernel<<<1, 1>>>((const unsigned int*)ei, (long long)in_sizes[1]);

    // ---- layer 1 ----
    zero_kernel<<<zeroBlks, 256>>>(agg, zeroN4);
    scatter_kernel<<<scatBlks, 256>>>(x, ei, E, agg);
    gemm_relu_kernel<true ><<<gemmBlks, 256>>>(x,  agg, W1a, b1a, tb, N);
    gemm_relu_kernel<false><<<gemmBlks, 256>>>(tb, nullptr, W1b, b1b, hb, N);

    // ---- layer 2 ----
    zero_kernel<<<zeroBlks, 256>>>(agg, zeroN4);
    scatter_kernel<<<scatBlks, 256>>>(hb, ei, E, agg);
    gemm_relu_kernel<true ><<<gemmBlks, 256>>>(hb, agg, W2a, b2a, tb, N);
    gemm_relu_kernel<false><<<gemmBlks, 256>>>(tb, nullptr, W2b, b2b, hb, N);

    // ---- pool + head ----
    zero_kernel<<<128, 256>>>(gp, 1024 * 32);
    pool_kernel<<<poolBlks, 256>>>(hb, batch, N, gp);
    head_kernel<<<1024, 128>>>(gp, Wl1, bl1, Wl2, bl2, out);
}

// round 2
// speedup vs baseline: 1.9687x; 1.9687x over previous
#include <cuda_runtime.h>

// ---------------- scratch (static device globals; no allocation) ------------
__device__ float g_agg[(size_t)100000 * 128];
__device__ float g_t  [(size_t)100000 * 128];
__device__ float g_h  [(size_t)100000 * 128];
__device__ int   g_deg   [100002];
__device__ int   g_rowptr[100002];
__device__ int   g_cursor[100002];
__device__ int   g_csr   [1700000];
__device__ int   g_idx64;   // 1 if indices are int64, 0 if int32

// ---------------- index dtype detection -------------------------------------
__global__ void detect_kernel(const unsigned int* __restrict__ w, long long n32) {
    long long nelem = n32 / 2;            // candidate int64 element count
    int is64 = 1;
    for (int i = 0; i < 256; i++) {
        long long e = (i * (nelem - 1)) / 255;
        if (w[2 * e + 1] != 0u) { is64 = 0; break; }
    }
    g_idx64 = is64;
}

__device__ __forceinline__ int load_idx(const void* p, long long i) {
    if (g_idx64) return (int)((const long long*)p)[i];
    return ((const int*)p)[i];
}

// ---------------- CSR build ---------------------------------------------------
__global__ void zero_int_kernel(int* __restrict__ p, int n) {
    int i = blockIdx.x * blockDim.x + threadIdx.x;
    if (i < n) p[i] = 0;
}

__global__ void hist_kernel(const void* __restrict__ ei, int E, int* __restrict__ deg) {
    int i = blockIdx.x * blockDim.x + threadIdx.x;
    if (i >= E) return;
    int dst = load_idx(ei, (long long)E + i);
    atomicAdd(&deg[dst], 1);
}

__global__ void scan_kernel(const int* __restrict__ deg, int* __restrict__ rowptr,
                            int* __restrict__ cursor, int N) {
    __shared__ int sums[1024];
    int t = threadIdx.x;
    int chunk = (N + 1023) / 1024;
    int s = t * chunk;
    int e = min(s + chunk, N);
    int sum = 0;
    for (int i = s; i < e; i++) sum += deg[i];
    sums[t] = sum;
    __syncthreads();
    for (int off = 1; off < 1024; off <<= 1) {
        int v = (t >= off) ? sums[t - off] : 0;
        __syncthreads();
        sums[t] += v;
        __syncthreads();
    }
    int run = (t == 0) ? 0 : sums[t - 1];
    for (int i = s; i < e; i++) {
        rowptr[i] = run;
        cursor[i] = run;
        run += deg[i];
    }
    if (t == 0) rowptr[N] = sums[1023];
}

__global__ void fill_kernel(const void* __restrict__ ei, int E,
                            int* __restrict__ cursor, int* __restrict__ csr) {
    int i = blockIdx.x * blockDim.x + threadIdx.x;
    if (i >= E) return;
    int src = load_idx(ei, i);
    int dst = load_idx(ei, (long long)E + i);
    int pos = atomicAdd(&cursor[dst], 1);
    csr[pos] = src;
}

// ---------------- gather aggregation: out[i] = h[i] + sum_{j in nbrs(i)} h[j] -
__global__ void gather_kernel(const float* __restrict__ h, const int* __restrict__ csr,
                              const int* __restrict__ rowptr, int N,
                              float* __restrict__ out) {
    int w = (blockIdx.x * blockDim.x + threadIdx.x) >> 5;
    int lane = threadIdx.x & 31;
    if (w >= N) return;
    int s = rowptr[w];
    int e = rowptr[w + 1];
    int q = lane * 4;
    float4 acc = *reinterpret_cast<const float4*>(h + (size_t)w * 128 + q);  // self (eps=0)
    int j = s;
    for (; j + 4 <= e; j += 4) {
        int s0 = csr[j], s1 = csr[j + 1], s2 = csr[j + 2], s3 = csr[j + 3];
        float4 v0 = *reinterpret_cast<const float4*>(h + (size_t)s0 * 128 + q);
        float4 v1 = *reinterpret_cast<const float4*>(h + (size_t)s1 * 128 + q);
        float4 v2 = *reinterpret_cast<const float4*>(h + (size_t)s2 * 128 + q);
        float4 v3 = *reinterpret_cast<const float4*>(h + (size_t)s3 * 128 + q);
        acc.x += v0.x + v1.x + v2.x + v3.x;
        acc.y += v0.y + v1.y + v2.y + v3.y;
        acc.z += v0.z + v1.z + v2.z + v3.z;
        acc.w += v0.w + v1.w + v2.w + v3.w;
    }
    for (; j < e; j++) {
        int src = csr[j];
        float4 v = *reinterpret_cast<const float4*>(h + (size_t)src * 128 + q);
        acc.x += v.x; acc.y += v.y; acc.z += v.z; acc.w += v.w;
    }
    *reinterpret_cast<float4*>(out + (size_t)w * 128 + q) = acc;
}

// ---------------- GEMM: C = relu(A @ W + bias) --------------------------------
__global__ __launch_bounds__(256, 2)
void gemm_relu_kernel(const float* __restrict__ A, const float* __restrict__ W,
                      const float* __restrict__ bias, float* __restrict__ C, int M) {
    __shared__ float As[16][128];
    __shared__ float Bs[16][128];

    const int tid  = threadIdx.x;
    const int row0 = blockIdx.x * 128;
    const int ty = tid >> 4;          // 0..15
    const int tx = tid & 15;          // 0..15

    const int lr   = tid >> 1;        // 0..127 : tile row
    const int lseg = (tid & 1) * 8;   // 0 or 8 : k offset
    const int bk   = tid >> 4;        // 0..15  : k row for W
    const int bn   = (tid & 15) * 8;  // 0..120 : col

    float acc[8][8];
#pragma unroll
    for (int i = 0; i < 8; i++)
#pragma unroll
        for (int j = 0; j < 8; j++) acc[i][j] = 0.f;

    const int  grow = row0 + lr;
    const bool rok  = grow < M;
    const float* Ap = A + (size_t)grow * 128;

    for (int kt = 0; kt < 128; kt += 16) {
        float4 a0, a1;
        if (rok) {
            a0 = *reinterpret_cast<const float4*>(Ap + kt + lseg);
            a1 = *reinterpret_cast<const float4*>(Ap + kt + lseg + 4);
        } else {
            a0 = make_float4(0.f, 0.f, 0.f, 0.f); a1 = a0;
        }
        As[lseg + 0][lr] = a0.x; As[lseg + 1][lr] = a0.y;
        As[lseg + 2][lr] = a0.z; As[lseg + 3][lr] = a0.w;
        As[lseg + 4][lr] = a1.x; As[lseg + 5][lr] = a1.y;
        As[lseg + 6][lr] = a1.z; As[lseg + 7][lr] = a1.w;

        *reinterpret_cast<float4*>(&Bs[bk][bn]) =
            *reinterpret_cast<const float4*>(W + (size_t)(kt + bk) * 128 + bn);
        *reinterpret_cast<float4*>(&Bs[bk][bn + 4]) =
            *reinterpret_cast<const float4*>(W + (size_t)(kt + bk) * 128 + bn + 4);

        __syncthreads();
#pragma unroll
        for (int kk = 0; kk < 16; kk++) {
            float a[8], b[8];
            *reinterpret_cast<float4*>(a)     = *reinterpret_cast<float4*>(&As[kk][ty * 4]);
            *reinterpret_cast<float4*>(a + 4) = *reinterpret_cast<float4*>(&As[kk][ty * 4 + 64]);
            *reinterpret_cast<float4*>(b)     = *reinterpret_cast<float4*>(&Bs[kk][tx * 4]);
            *reinterpret_cast<float4*>(b + 4) = *reinterpret_cast<float4*>(&Bs[kk][tx * 4 + 64]);
#pragma unroll
            for (int i = 0; i < 8; i++)
#pragma unroll
                for (int j = 0; j < 8; j++) acc[i][j] += a[i] * b[j];
        }
        __syncthreads();
    }

#pragma unroll
    for (int i = 0; i < 8; i++) {
        int r = row0 + ty * 4 + (i >> 2) * 64 + (i & 3);
        if (r < M) {
#pragma unroll
            for (int jj = 0; jj < 2; jj++) {
                int c = tx * 4 + jj * 64;
                float4 o;
                o.x = fmaxf(acc[i][jj * 4 + 0] + bias[c + 0], 0.f);
                o.y = fmaxf(acc[i][jj * 4 + 1] + bias[c + 1], 0.f);
                o.z = fmaxf(acc[i][jj * 4 + 2] + bias[c + 2], 0.f);
                o.w = fmaxf(acc[i][jj * 4 + 3] + bias[c + 3], 0.f);
                *reinterpret_cast<float4*>(C + (size_t)r * 128 + c) = o;
            }
        }
    }
}

// ---------------- fused pool + classifier head + log_softmax ------------------
__device__ __forceinline__ int lower_bound_batch(const void* batch, int N, int val) {
    int lo = 0, hi = N;
    while (lo < hi) {
        int mid = (lo + hi) >> 1;
        if (load_idx(batch, mid) < val) lo = mid + 1; else hi = mid;
    }
    return lo;
}

__global__ void head_kernel(const float* __restrict__ h, const void* __restrict__ batch,
                            int N,
                            const float* __restrict__ Wl1, const float* __restrict__ bl1,
                            const float* __restrict__ Wl2, const float* __restrict__ bl2,
                            float* __restrict__ out) {
    __shared__ float row[128];
    __shared__ float hid[128];
    __shared__ float lg[10];
    __shared__ float red[2];
    int gi = blockIdx.x;
    int t = threadIdx.x;

    // pooling over the (sorted) node range of this graph
    int s = lower_bound_batch(batch, N, gi);
    int e = lower_bound_batch(batch, N, gi + 1);
    float sum = 0.f;
    for (int n = s; n < e; n++) sum += h[(size_t)n * 128 + t];
    row[t] = sum;
    __syncthreads();

    float v1 = bl1[t];
#pragma unroll 8
    for (int k = 0; k < 128; k++) v1 += row[k] * Wl1[k * 128 + t];
    hid[t] = fmaxf(v1, 0.f);
    __syncthreads();

    if (t < 10) {
        float v = bl2[t];
#pragma unroll 8
        for (int k = 0; k < 128; k++) v += hid[k] * Wl2[k * 10 + t];
        lg[t] = v;
    }
    __syncthreads();

    if (t == 0) {
        float m = lg[0];
        for (int i = 1; i < 10; i++) m = fmaxf(m, lg[i]);
        float se = 0.f;
        for (int i = 0; i < 10; i++) se += expf(lg[i] - m);
        red[0] = m;
        red[1] = logf(se);
    }
    __syncthreads();

    if (t < 10) out[(size_t)gi * 10 + t] = lg[t] - red[0] - red[1];
}

// ---------------- launch ------------------------------------------------------
extern "C" void kernel_launch(void* const* d_in, const int* in_sizes, int n_in,
                              void* d_out, int out_size) {
    const float* x     = (const float*)d_in[0];
    const void*  ei    = d_in[1];
    const void*  batch = d_in[2];
    const float* W1a = (const float*)d_in[3];
    const float* b1a = (const float*)d_in[4];
    const float* W1b = (const float*)d_in[5];
    const float* b1b = (const float*)d_in[6];
    const float* W2a = (const float*)d_in[7];
    const float* b2a = (const float*)d_in[8];
    const float* W2b = (const float*)d_in[9];
    const float* b2b = (const float*)d_in[10];
    const float* Wl1 = (const float*)d_in[11];
    const float* bl1 = (const float*)d_in[12];
    const float* Wl2 = (const float*)d_in[13];
    const float* bl2 = (const float*)d_in[14];
    float* out = (float*)d_out;

    const int N = in_sizes[0] / 128;
    const int E = in_sizes[1] / 2;

    float *agg, *tb, *hb;
    int *deg, *rowptr, *cursor, *csr;
    cudaGetSymbolAddress((void**)&agg,    g_agg);
    cudaGetSymbolAddress((void**)&tb,     g_t);
    cudaGetSymbolAddress((void**)&hb,     g_h);
    cudaGetSymbolAddress((void**)&deg,    g_deg);
    cudaGetSymbolAddress((void**)&rowptr, g_rowptr);
    cudaGetSymbolAddress((void**)&cursor, g_cursor);
    cudaGetSymbolAddress((void**)&csr,    g_csr);

    const int edgeBlks   = (E + 255) / 256;
    const int gatherBlks = (N * 32 + 255) / 256;   // one warp per node
    const int gemmBlks   = (N + 127) / 128;

    detect_kernel<<<1, 1>>>((const unsigned int*)ei, (long long)in_sizes[1]);

    // ---- CSR build (once; shared by both layers) ----
    zero_int_kernel<<<(N + 1 + 255) / 256, 256>>>(deg, N + 1);
    hist_kernel<<<edgeBlks, 256>>>(ei, E, deg);
    scan_kernel<<<1, 1024>>>(deg, rowptr, cursor, N);
    fill_kernel<<<edgeBlks, 256>>>(ei, E, cursor, csr);

    // ---- layer 1 ----
    gather_kernel<<<gatherBlks, 256>>>(x, csr, rowptr, N, agg);
    gemm_relu_kernel<<<gemmBlks, 256>>>(agg, W1a, b1a, tb, N);
    gemm_relu_kernel<<<gemmBlks, 256>>>(tb,  W1b, b1b, hb, N);

    // ---- layer 2 ----
    gather_kernel<<<gatherBlks, 256>>>(hb, csr, rowptr, N, agg);
    gemm_relu_kernel<<<gemmBlks, 256>>>(agg, W2a, b2a, tb, N);
    gemm_relu_kernel<<<gemmBlks, 256>>>(tb,  W2b, b2b, hb, N);

    // ---- fused pool + head ----
    head_kernel<<<1024, 128>>>(hb, batch, N, Wl1, bl1, Wl2, bl2, out);
}

// round 3
// speedup vs baseline: 3.6483x; 1.8532x over previous
#include <cuda_runtime.h>
#include <cstdint>

// ---------------- scratch (static device globals; no allocation) ------------
__device__ float g_agg[(size_t)100000 * 128];
__device__ float g_t  [(size_t)100000 * 128];
__device__ float g_h  [(size_t)100000 * 128];
__device__ int   g_deg   [100002];
__device__ int   g_rowptr[100002];
__device__ int   g_cursor[100002];
__device__ int   g_csr   [1700000];
__device__ int   g_bsum  [128];
__device__ int   g_boff  [128];
__device__ float g_wf[4][16384];   // fragment-ready tf32 weights
__device__ int   g_idx64;

// ---------------- index dtype detection (parallel) ---------------------------
__global__ void detect_kernel(const unsigned int* __restrict__ w, long long n32) {
    long long nelem = n32 / 2;
    int t = threadIdx.x;
    long long e = ((long long)t * (nelem - 1)) / 255;
    int ok = (t < 256) ? (w[2 * e + 1] == 0u) : 1;
    int all = __syncthreads_and(ok);
    if (t == 0) g_idx64 = all ? 1 : 0;
}

__device__ __forceinline__ int load_idx(const void* p, long long i) {
    if (g_idx64) return (int)((const long long*)p)[i];
    return ((const int*)p)[i];
}

// ---------------- CSR build ---------------------------------------------------
__global__ void zero_int_kernel(int* __restrict__ p, int n) {
    int i = blockIdx.x * blockDim.x + threadIdx.x;
    if (i < n) p[i] = 0;
}

__global__ void hist_kernel(const void* __restrict__ ei, int E, int* __restrict__ deg) {
    int i = blockIdx.x * blockDim.x + threadIdx.x;
    if (i >= E) return;
    int dst = load_idx(ei, (long long)E + i);
    atomicAdd(&deg[dst], 1);
}

// phase 1: per-block partial sums over contiguous chunks
__global__ void scan_partial_kernel(const int* __restrict__ deg, int N, int CH,
                                    int* __restrict__ bsum) {
    __shared__ int red[256];
    int b = blockIdx.x, t = threadIdx.x;
    int s = b * CH, e = min(s + CH, N);
    int sum = 0;
    for (int i = s + t; i < e; i += 256) sum += deg[i];
    red[t] = sum;
    __syncthreads();
    for (int off = 128; off > 0; off >>= 1) {
        if (t < off) red[t] += red[t + off];
        __syncthreads();
    }
    if (t == 0) bsum[b] = red[0];
}

// phase 2: exclusive scan of 128 block sums (1 block)
__global__ void scan_bsum_kernel(const int* __restrict__ bsum, int* __restrict__ boff,
                                 int* __restrict__ rowptr, int N) {
    __shared__ int s[128];
    int t = threadIdx.x;
    s[t] = bsum[t];
    __syncthreads();
    for (int off = 1; off < 128; off <<= 1) {
        int v = (t >= off) ? s[t - off] : 0;
        __syncthreads();
        s[t] += v;
        __syncthreads();
    }
    boff[t] = (t == 0) ? 0 : s[t - 1];
    if (t == 127) rowptr[N] = s[127];
}

// phase 3: per-block local exclusive scan + write rowptr/cursor
__global__ void scan_write_kernel(const int* __restrict__ deg, int N, int CH,
                                  const int* __restrict__ boff,
                                  int* __restrict__ rowptr, int* __restrict__ cursor) {
    __shared__ int ts[256];
    int b = blockIdx.x, t = threadIdx.x;
    int s = b * CH, e = min(s + CH, N);
    int tc = (CH + 255) / 256;
    int ms = s + t * tc, me = min(ms + tc, e);
    int sum = 0;
    for (int i = ms; i < me; i++) sum += deg[i];
    ts[t] = sum;
    __syncthreads();
    for (int off = 1; off < 256; off <<= 1) {
        int v = (t >= off) ? ts[t - off] : 0;
        __syncthreads();
        ts[t] += v;
        __syncthreads();
    }
    int run = boff[b] + ((t == 0) ? 0 : ts[t - 1]);
    for (int i = ms; i < me; i++) {
        rowptr[i] = run;
        cursor[i] = run;
        run += deg[i];
    }
}

__global__ void fill_kernel(const void* __restrict__ ei, int E,
                            int* __restrict__ cursor, int* __restrict__ csr) {
    int i = blockIdx.x * blockDim.x + threadIdx.x;
    if (i >= E) return;
    int src = load_idx(ei, i);
    int dst = load_idx(ei, (long long)E + i);
    int pos = atomicAdd(&cursor[dst], 1);
    csr[pos] = src;
}

// ---------------- gather aggregation: out[i] = h[i] + sum_{j in nbrs(i)} h[j] -
__global__ void gather_kernel(const float* __restrict__ h, const int* __restrict__ csr,
                              const int* __restrict__ rowptr, int N,
                              float* __restrict__ out) {
    int w = (blockIdx.x * blockDim.x + threadIdx.x) >> 5;
    int lane = threadIdx.x & 31;
    if (w >= N) return;
    int s = rowptr[w];
    int e = rowptr[w + 1];
    int q = lane * 4;
    float4 acc = *reinterpret_cast<const float4*>(h + (size_t)w * 128 + q);
    int j = s;
    for (; j + 4 <= e; j += 4) {
        int s0 = csr[j], s1 = csr[j + 1], s2 = csr[j + 2], s3 = csr[j + 3];
        float4 v0 = *reinterpret_cast<const float4*>(h + (size_t)s0 * 128 + q);
        float4 v1 = *reinterpret_cast<const float4*>(h + (size_t)s1 * 128 + q);
        float4 v2 = *reinterpret_cast<const float4*>(h + (size_t)s2 * 128 + q);
        float4 v3 = *reinterpret_cast<const float4*>(h + (size_t)s3 * 128 + q);
        acc.x += v0.x + v1.x + v2.x + v3.x;
        acc.y += v0.y + v1.y + v2.y + v3.y;
        acc.z += v0.z + v1.z + v2.z + v3.z;
        acc.w += v0.w + v1.w + v2.w + v3.w;
    }
    for (; j < e; j++) {
        int src = csr[j];
        float4 v = *reinterpret_cast<const float4*>(h + (size_t)src * 128 + q);
        acc.x += v.x; acc.y += v.y; acc.z += v.z; acc.w += v.w;
    }
    *reinterpret_cast<float4*>(out + (size_t)w * 128 + q) = acc;
}

// ---------------- weight transform: row-major fp32 -> fragment-ready tf32 ----
// Wf[((kt*16 + nt)*2 + r)*32 + lane] = tf32(W[(kt*8 + (lane&3) + 4r)*128 + nt*8 + lane/4])
__global__ void wtransform_kernel(const float* __restrict__ W, float* __restrict__ Wf) {
    int o = blockIdx.x * blockDim.x + threadIdx.x;   // 0..16383
    int lane = o & 31;
    int r    = (o >> 5) & 1;
    int nt   = (o >> 6) & 15;
    int kt   = o >> 10;
    int k = kt * 8 + (lane & 3) + r * 4;
    int n = nt * 8 + (lane >> 2);
    float v = W[k * 128 + n];
    uint32_t u;
    asm("cvt.rna.tf32.f32 %0, %1;" : "=r"(u) : "f"(v));
    Wf[o] = __uint_as_float(u);
}

// ---------------- TF32 tensor-core GEMM: C = relu(A @ W + bias) --------------
// Block: 256 threads (8 warps). Each warp: 16 rows x 128 cols. Block: 128 rows.
// W fragments staged in 64KB dynamic smem once; mainloop is sync-free.
__device__ __forceinline__ void mma_tf32(float* c, uint32_t a0, uint32_t a1,
                                         uint32_t a2, uint32_t a3,
                                         uint32_t b0, uint32_t b1) {
    asm volatile(
        "mma.sync.aligned.m16n8k8.row.col.f32.tf32.tf32.f32 "
        "{%0,%1,%2,%3}, {%4,%5,%6,%7}, {%8,%9}, {%0,%1,%2,%3};"
        : "+f"(c[0]), "+f"(c[1]), "+f"(c[2]), "+f"(c[3])
        : "r"(a0), "r"(a1), "r"(a2), "r"(a3), "r"(b0), "r"(b1));
}

__global__ __launch_bounds__(256)
void gemm_tf32_kernel(const float* __restrict__ A, const float* __restrict__ Wf,
                      const float* __restrict__ bias, float* __restrict__ C, int M) {
    extern __shared__ float ws[];   // 16384 floats = 64KB
    const int tid = threadIdx.x;

    float4* ws4 = reinterpret_cast<float4*>(ws);
    const float4* wf4 = reinterpret_cast<const float4*>(Wf);
#pragma unroll
    for (int i = 0; i < 16; i++) ws4[tid + 256 * i] = wf4[tid + 256 * i];
    __syncthreads();

    const int warp = tid >> 5, lane = tid & 31;
    const int g = lane >> 2, t = lane & 3;
    const int row0 = blockIdx.x * 128 + warp * 16;
    const int rg  = row0 + g;
    const int rg8 = rg + 8;
    const float* Ag  = A + (size_t)min(rg,  M - 1) * 128;
    const float* Ag8 = A + (size_t)min(rg8, M - 1) * 128;

    float acc[16][4];
#pragma unroll
    for (int i = 0; i < 16; i++)
#pragma unroll
        for (int j = 0; j < 4; j++) acc[i][j] = 0.f;

    // software-pipelined A fragment loads
    float na0 = Ag[t], na1 = Ag8[t], na2 = Ag[t + 4], na3 = Ag8[t + 4];

#pragma unroll
    for (int kt = 0; kt < 16; kt++) {
        uint32_t a0, a1, a2, a3;
        asm("cvt.rna.tf32.f32 %0, %1;" : "=r"(a0) : "f"(na0));
        asm("cvt.rna.tf32.f32 %0, %1;" : "=r"(a1) : "f"(na1));
        asm("cvt.rna.tf32.f32 %0, %1;" : "=r"(a2) : "f"(na2));
        asm("cvt.rna.tf32.f32 %0, %1;" : "=r"(a3) : "f"(na3));
        if (kt < 15) {
            int k1 = (kt + 1) * 8;
            na0 = Ag[k1 + t]; na1 = Ag8[k1 + t];
            na2 = Ag[k1 + t + 4]; na3 = Ag8[k1 + t + 4];
        }
        const float* wbase = ws + kt * 1024;
#pragma unroll
        for (int nt = 0; nt < 16; nt++) {
            uint32_t b0 = __float_as_uint(wbase[nt * 64 + lane]);
            uint32_t b1 = __float_as_uint(wbase[nt * 64 + 32 + lane]);
            mma_tf32(acc[nt], a0, a1, a2, a3, b0, b1);
        }
    }

#pragma unroll
    for (int nt = 0; nt < 16; nt++) {
        int col = nt * 8 + 2 * t;
        float bx = bias[col], by = bias[col + 1];
        if (rg < M) {
            float2 o = { fmaxf(acc[nt][0] + bx, 0.f), fmaxf(acc[nt][1] + by, 0.f) };
            *reinterpret_cast<float2*>(C + (size_t)rg * 128 + col) = o;
        }
        if (rg8 < M) {
            float2 o = { fmaxf(acc[nt][2] + bx, 0.f), fmaxf(acc[nt][3] + by, 0.f) };
            *reinterpret_cast<float2*>(C + (size_t)rg8 * 128 + col) = o;
        }
    }
}

// ---------------- fused pool + classifier head + log_softmax ------------------
__device__ __forceinline__ int lower_bound_batch(const void* batch, int N, int val) {
    int lo = 0, hi = N;
    while (lo < hi) {
        int mid = (lo + hi) >> 1;
        if (load_idx(batch, mid) < val) lo = mid + 1; else hi = mid;
    }
    return lo;
}

__global__ void head_kernel(const float* __restrict__ h, const void* __restrict__ batch,
                            int N,
                            const float* __restrict__ Wl1, const float* __restrict__ bl1,
                            const float* __restrict__ Wl2, const float* __restrict__ bl2,
                            float* __restrict__ out) {
    __shared__ float row[128];
    __shared__ float hid[128];
    __shared__ float lg[10];
    __shared__ float red[2];
    int gi = blockIdx.x;
    int t = threadIdx.x;

    int s = lower_bound_batch(batch, N, gi);
    int e = lower_bound_batch(batch, N, gi + 1);
    float sum = 0.f;
    for (int n = s; n < e; n++) sum += h[(size_t)n * 128 + t];
    row[t] = sum;
    __syncthreads();

    float v1 = bl1[t];
#pragma unroll 8
    for (int k = 0; k < 128; k++) v1 += row[k] * Wl1[k * 128 + t];
    hid[t] = fmaxf(v1, 0.f);
    __syncthreads();

    if (t < 10) {
        float v = bl2[t];
#pragma unroll 8
        for (int k = 0; k < 128; k++) v += hid[k] * Wl2[k * 10 + t];
        lg[t] = v;
    }
    __syncthreads();

    if (t == 0) {
        float m = lg[0];
        for (int i = 1; i < 10; i++) m = fmaxf(m, lg[i]);
        float se = 0.f;
        for (int i = 0; i < 10; i++) se += expf(lg[i] - m);
        red[0] = m;
        red[1] = logf(se);
    }
    __syncthreads();

    if (t < 10) out[(size_t)gi * 10 + t] = lg[t] - red[0] - red[1];
}

// ---------------- launch ------------------------------------------------------
extern "C" void kernel_launch(void* const* d_in, const int* in_sizes, int n_in,
                              void* d_out, int out_size) {
    const float* x     = (const float*)d_in[0];
    const void*  ei    = d_in[1];
    const void*  batch = d_in[2];
    const float* W1a = (const float*)d_in[3];
    const float* b1a = (const float*)d_in[4];
    const float* W1b = (const float*)d_in[5];
    const float* b1b = (const float*)d_in[6];
    const float* W2a = (const float*)d_in[7];
    const float* b2a = (const float*)d_in[8];
    const float* W2b = (const float*)d_in[9];
    const float* b2b = (const float*)d_in[10];
    const float* Wl1 = (const float*)d_in[11];
    const float* bl1 = (const float*)d_in[12];
    const float* Wl2 = (const float*)d_in[13];
    const float* bl2 = (const float*)d_in[14];
    float* out = (float*)d_out;

    const int N = in_sizes[0] / 128;
    const int E = in_sizes[1] / 2;

    float *agg, *tb, *hb, *wf;
    int *deg, *rowptr, *cursor, *csr, *bsum, *boff;
    cudaGetSymbolAddress((void**)&agg,    g_agg);
    cudaGetSymbolAddress((void**)&tb,     g_t);
    cudaGetSymbolAddress((void**)&hb,     g_h);
    cudaGetSymbolAddress((void**)&deg,    g_deg);
    cudaGetSymbolAddress((void**)&rowptr, g_rowptr);
    cudaGetSymbolAddress((void**)&cursor, g_cursor);
    cudaGetSymbolAddress((void**)&csr,    g_csr);
    cudaGetSymbolAddress((void**)&bsum,   g_bsum);
    cudaGetSymbolAddress((void**)&boff,   g_boff);
    cudaGetSymbolAddress((void**)&wf,     g_wf);

    static bool smem_set = false;
    if (!smem_set) {
        cudaFuncSetAttribute(gemm_tf32_kernel,
                             cudaFuncAttributeMaxDynamicSharedMemorySize, 65536);
        smem_set = true;
    }

    const int edgeBlks   = (E + 255) / 256;
    const int gatherBlks = (N * 32 + 255) / 256;
    const int gemmBlks   = (N + 127) / 128;
    const int CH         = (N + 127) / 128;

    detect_kernel<<<1, 256>>>((const unsigned int*)ei, (long long)in_sizes[1]);

    // weight transforms (independent of detect)
    wtransform_kernel<<<64, 256>>>(W1a, wf + 0 * 16384);
    wtransform_kernel<<<64, 256>>>(W1b, wf + 1 * 16384);
    wtransform_kernel<<<64, 256>>>(W2a, wf + 2 * 16384);
    wtransform_kernel<<<64, 256>>>(W2b, wf + 3 * 16384);

    // ---- CSR build ----
    zero_int_kernel<<<(N + 1 + 255) / 256, 256>>>(deg, N + 1);
    hist_kernel<<<edgeBlks, 256>>>(ei, E, deg);
    scan_partial_kernel<<<128, 256>>>(deg, N, CH, bsum);
    scan_bsum_kernel<<<1, 128>>>(bsum, boff, rowptr, N);
    scan_write_kernel<<<128, 256>>>(deg, N, CH, boff, rowptr, cursor);
    fill_kernel<<<edgeBlks, 256>>>(ei, E, cursor, csr);

    // ---- layer 1 ----
    gather_kernel<<<gatherBlks, 256>>>(x, csr, rowptr, N, agg);
    gemm_tf32_kernel<<<gemmBlks, 256, 65536>>>(agg, wf + 0 * 16384, b1a, tb, N);
    gemm_tf32_kernel<<<gemmBlks, 256, 65536>>>(tb,  wf + 1 * 16384, b1b, hb, N);

    // ---- layer 2 ----
    gather_kernel<<<gatherBlks, 256>>>(hb, csr, rowptr, N, agg);
    gemm_tf32_kernel<<<gemmBlks, 256, 65536>>>(agg, wf + 2 * 16384, b2a, tb, N);
    gemm_tf32_kernel<<<gemmBlks, 256, 65536>>>(tb,  wf + 3 * 16384, b2b, hb, N);

    // ---- fused pool + head ----
    head_kernel<<<1024, 128>>>(hb, batch, N, Wl1, bl1, Wl2, bl2, out);
}

// round 4
// speedup vs baseline: 3.8427x; 1.0533x over previous
#include <cuda_runtime.h>
#include <cstdint>

// ---------------- scratch (static device globals; no allocation) ------------
__device__ float g_agg[(size_t)100000 * 128];
__device__ float g_h  [(size_t)100000 * 128];
__device__ int   g_deg   [100002];
__device__ int   g_rowptr[100002];
__device__ int   g_cursor[100002];
__device__ int   g_csr   [1700000];
__device__ int   g_bsum  [128];
__device__ int   g_boff  [128];
__device__ float g_wf[4][16384];   // fragment-ready tf32 weights
__device__ int   g_idx64;

// ---------------- index dtype detection (parallel) ---------------------------
__global__ void detect_kernel(const unsigned int* __restrict__ w, long long n32) {
    long long nelem = n32 / 2;
    int t = threadIdx.x;
    long long e = ((long long)t * (nelem - 1)) / 255;
    int ok = (t < 256) ? (w[2 * e + 1] == 0u) : 1;
    int all = __syncthreads_and(ok);
    if (t == 0) g_idx64 = all ? 1 : 0;
}

__device__ __forceinline__ int load_idx(const void* p, long long i) {
    if (g_idx64) return (int)((const long long*)p)[i];
    return ((const int*)p)[i];
}

// ---------------- CSR build ---------------------------------------------------
__global__ void zero_int_kernel(int* __restrict__ p, int n) {
    int i = blockIdx.x * blockDim.x + threadIdx.x;
    if (i < n) p[i] = 0;
}

__global__ void hist_kernel(const void* __restrict__ ei, int E, int* __restrict__ deg) {
    int i = blockIdx.x * blockDim.x + threadIdx.x;
    if (i >= E) return;
    int dst = load_idx(ei, (long long)E + i);
    atomicAdd(&deg[dst], 1);
}

__global__ void scan_partial_kernel(const int* __restrict__ deg, int N, int CH,
                                    int* __restrict__ bsum) {
    __shared__ int red[256];
    int b = blockIdx.x, t = threadIdx.x;
    int s = b * CH, e = min(s + CH, N);
    int sum = 0;
    for (int i = s + t; i < e; i += 256) sum += deg[i];
    red[t] = sum;
    __syncthreads();
    for (int off = 128; off > 0; off >>= 1) {
        if (t < off) red[t] += red[t + off];
        __syncthreads();
    }
    if (t == 0) bsum[b] = red[0];
}

__global__ void scan_bsum_kernel(const int* __restrict__ bsum, int* __restrict__ boff,
                                 int* __restrict__ rowptr, int N) {
    __shared__ int s[128];
    int t = threadIdx.x;
    s[t] = bsum[t];
    __syncthreads();
    for (int off = 1; off < 128; off <<= 1) {
        int v = (t >= off) ? s[t - off] : 0;
        __syncthreads();
        s[t] += v;
        __syncthreads();
    }
    boff[t] = (t == 0) ? 0 : s[t - 1];
    if (t == 127) rowptr[N] = s[127];
}

__global__ void scan_write_kernel(const int* __restrict__ deg, int N, int CH,
                                  const int* __restrict__ boff,
                                  int* __restrict__ rowptr, int* __restrict__ cursor) {
    __shared__ int ts[256];
    int b = blockIdx.x, t = threadIdx.x;
    int s = b * CH, e = min(s + CH, N);
    int tc = (CH + 255) / 256;
    int ms = s + t * tc, me = min(ms + tc, e);
    int sum = 0;
    for (int i = ms; i < me; i++) sum += deg[i];
    ts[t] = sum;
    __syncthreads();
    for (int off = 1; off < 256; off <<= 1) {
        int v = (t >= off) ? ts[t - off] : 0;
        __syncthreads();
        ts[t] += v;
        __syncthreads();
    }
    int run = boff[b] + ((t == 0) ? 0 : ts[t - 1]);
    for (int i = ms; i < me; i++) {
        rowptr[i] = run;
        cursor[i] = run;
        run += deg[i];
    }
}

__global__ void fill_kernel(const void* __restrict__ ei, int E,
                            int* __restrict__ cursor, int* __restrict__ csr) {
    int i = blockIdx.x * blockDim.x + threadIdx.x;
    if (i >= E) return;
    int src = load_idx(ei, i);
    int dst = load_idx(ei, (long long)E + i);
    int pos = atomicAdd(&cursor[dst], 1);
    csr[pos] = src;
}

// ---------------- gather aggregation: out[i] = h[i] + sum_{j in nbrs(i)} h[j] -
__global__ void gather_kernel(const float* __restrict__ h, const int* __restrict__ csr,
                              const int* __restrict__ rowptr, int N,
                              float* __restrict__ out) {
    int w = (blockIdx.x * blockDim.x + threadIdx.x) >> 5;
    int lane = threadIdx.x & 31;
    if (w >= N) return;
    int s = rowptr[w];
    int e = rowptr[w + 1];
    int q = lane * 4;
    float4 acc = *reinterpret_cast<const float4*>(h + (size_t)w * 128 + q);
    int j = s;
    for (; j + 4 <= e; j += 4) {
        int s0 = csr[j], s1 = csr[j + 1], s2 = csr[j + 2], s3 = csr[j + 3];
        float4 v0 = *reinterpret_cast<const float4*>(h + (size_t)s0 * 128 + q);
        float4 v1 = *reinterpret_cast<const float4*>(h + (size_t)s1 * 128 + q);
        float4 v2 = *reinterpret_cast<const float4*>(h + (size_t)s2 * 128 + q);
        float4 v3 = *reinterpret_cast<const float4*>(h + (size_t)s3 * 128 + q);
        acc.x += v0.x + v1.x + v2.x + v3.x;
        acc.y += v0.y + v1.y + v2.y + v3.y;
        acc.z += v0.z + v1.z + v2.z + v3.z;
        acc.w += v0.w + v1.w + v2.w + v3.w;
    }
    for (; j < e; j++) {
        int src = csr[j];
        float4 v = *reinterpret_cast<const float4*>(h + (size_t)src * 128 + q);
        acc.x += v.x; acc.y += v.y; acc.z += v.z; acc.w += v.w;
    }
    *reinterpret_cast<float4*>(out + (size_t)w * 128 + q) = acc;
}

// ---------------- weight transform: row-major fp32 -> fragment-ready tf32 ----
__global__ void wtransform_kernel(const float* __restrict__ W, float* __restrict__ Wf) {
    int o = blockIdx.x * blockDim.x + threadIdx.x;   // 0..16383
    int lane = o & 31;
    int r    = (o >> 5) & 1;
    int nt   = (o >> 6) & 15;
    int kt   = o >> 10;
    int k = kt * 8 + (lane & 3) + r * 4;
    int n = nt * 8 + (lane >> 2);
    float v = W[k * 128 + n];
    uint32_t u;
    asm("cvt.rna.tf32.f32 %0, %1;" : "=r"(u) : "f"(v));
    Wf[o] = __uint_as_float(u);
}

// ---------------- fused MLP: C = relu(relu(A@Wa+ba)@Wb+bb) -------------------
// 256 threads (8 warps), 128 rows per block. Wa+Wb fragments staged in smem
// (128KB); each warp keeps its 16x128 intermediate tile in private padded smem
// (stride 136 -> conflict-free LDS). Mainloops are sync-free.
__device__ __forceinline__ void mma_tf32(float* c, uint32_t a0, uint32_t a1,
                                         uint32_t a2, uint32_t a3,
                                         uint32_t b0, uint32_t b1) {
    asm volatile(
        "mma.sync.aligned.m16n8k8.row.col.f32.tf32.tf32.f32 "
        "{%0,%1,%2,%3}, {%4,%5,%6,%7}, {%8,%9}, {%0,%1,%2,%3};"
        : "+f"(c[0]), "+f"(c[1]), "+f"(c[2]), "+f"(c[3])
        : "r"(a0), "r"(a1), "r"(a2), "r"(a3), "r"(b0), "r"(b1));
}

#define T_STRIDE 136
#define MLP_SMEM_FLOATS (32768 + 8 * 16 * T_STRIDE)

__global__ __launch_bounds__(256)
void mlp_fused_kernel(const float* __restrict__ A,
                      const float* __restrict__ Wfa, const float* __restrict__ Wfb,
                      const float* __restrict__ ba, const float* __restrict__ bb,
                      float* __restrict__ C, int M) {
    extern __shared__ float ws[];
    float* wsa = ws;            // 16384 floats
    float* wsb = ws + 16384;    // 16384 floats
    const int tid = threadIdx.x;

    {   // stage both weight fragment sets (128KB)
        float4* d = reinterpret_cast<float4*>(ws);
        const float4* sa = reinterpret_cast<const float4*>(Wfa);
        const float4* sb = reinterpret_cast<const float4*>(Wfb);
#pragma unroll
        for (int i = 0; i < 16; i++) d[tid + 256 * i]        = sa[tid + 256 * i];
#pragma unroll
        for (int i = 0; i < 16; i++) d[4096 + tid + 256 * i] = sb[tid + 256 * i];
    }
    __syncthreads();

    const int warp = tid >> 5, lane = tid & 31;
    const int g = lane >> 2, t = lane & 3;
    const int row0 = blockIdx.x * 128 + warp * 16;
    const int rg  = row0 + g;
    const int rg8 = rg + 8;
    const float* Ag  = A + (size_t)min(rg,  M - 1) * 128;
    const float* Ag8 = A + (size_t)min(rg8, M - 1) * 128;
    float* tw = ws + 32768 + warp * (16 * T_STRIDE);

    float acc[16][4];
#pragma unroll
    for (int i = 0; i < 16; i++)
#pragma unroll
        for (int j = 0; j < 4; j++) acc[i][j] = 0.f;

    // ---- GEMM 1: acc = A @ Wa ----
    float na0 = Ag[t], na1 = Ag8[t], na2 = Ag[t + 4], na3 = Ag8[t + 4];
#pragma unroll
    for (int kt = 0; kt < 16; kt++) {
        uint32_t a0, a1, a2, a3;
        asm("cvt.rna.tf32.f32 %0, %1;" : "=r"(a0) : "f"(na0));
        asm("cvt.rna.tf32.f32 %0, %1;" : "=r"(a1) : "f"(na1));
        asm("cvt.rna.tf32.f32 %0, %1;" : "=r"(a2) : "f"(na2));
        asm("cvt.rna.tf32.f32 %0, %1;" : "=r"(a3) : "f"(na3));
        if (kt < 15) {
            int k1 = (kt + 1) * 8;
            na0 = Ag[k1 + t]; na1 = Ag8[k1 + t];
            na2 = Ag[k1 + t + 4]; na3 = Ag8[k1 + t + 4];
        }
        const float* wbase = wsa + kt * 1024;
#pragma unroll
        for (int nt = 0; nt < 16; nt++) {
            uint32_t b0 = __float_as_uint(wbase[nt * 64 + lane]);
            uint32_t b1 = __float_as_uint(wbase[nt * 64 + 32 + lane]);
            mma_tf32(acc[nt], a0, a1, a2, a3, b0, b1);
        }
    }

    // ---- t = relu(acc + ba) -> warp-private smem tile ----
#pragma unroll
    for (int nt = 0; nt < 16; nt++) {
        int col = nt * 8 + 2 * t;
        float bx = ba[col], by = ba[col + 1];
        float2 o0 = { fmaxf(acc[nt][0] + bx, 0.f), fmaxf(acc[nt][1] + by, 0.f) };
        float2 o1 = { fmaxf(acc[nt][2] + bx, 0.f), fmaxf(acc[nt][3] + by, 0.f) };
        *reinterpret_cast<float2*>(tw + g * T_STRIDE + col)       = o0;
        *reinterpret_cast<float2*>(tw + (g + 8) * T_STRIDE + col) = o1;
    }
    __syncwarp();

    // ---- GEMM 2: acc = t @ Wb ----
#pragma unroll
    for (int i = 0; i < 16; i++)
#pragma unroll
        for (int j = 0; j < 4; j++) acc[i][j] = 0.f;

#pragma unroll
    for (int kt = 0; kt < 16; kt++) {
        int kb = kt * 8;
        uint32_t a0, a1, a2, a3;
        asm("cvt.rna.tf32.f32 %0, %1;" : "=r"(a0) : "f"(tw[g * T_STRIDE + kb + t]));
        asm("cvt.rna.tf32.f32 %0, %1;" : "=r"(a1) : "f"(tw[(g + 8) * T_STRIDE + kb + t]));
        asm("cvt.rna.tf32.f32 %0, %1;" : "=r"(a2) : "f"(tw[g * T_STRIDE + kb + t + 4]));
        asm("cvt.rna.tf32.f32 %0, %1;" : "=r"(a3) : "f"(tw[(g + 8) * T_STRIDE + kb + t + 4]));
        const float* wbase = wsb + kt * 1024;
#pragma unroll
        for (int nt = 0; nt < 16; nt++) {
            uint32_t b0 = __float_as_uint(wbase[nt * 64 + lane]);
            uint32_t b1 = __float_as_uint(wbase[nt * 64 + 32 + lane]);
            mma_tf32(acc[nt], a0, a1, a2, a3, b0, b1);
        }
    }

    // ---- C = relu(acc + bb) ----
#pragma unroll
    for (int nt = 0; nt < 16; nt++) {
        int col = nt * 8 + 2 * t;
        float bx = bb[col], by = bb[col + 1];
        if (rg < M) {
            float2 o = { fmaxf(acc[nt][0] + bx, 0.f), fmaxf(acc[nt][1] + by, 0.f) };
            *reinterpret_cast<float2*>(C + (size_t)rg * 128 + col) = o;
        }
        if (rg8 < M) {
            float2 o = { fmaxf(acc[nt][2] + bx, 0.f), fmaxf(acc[nt][3] + by, 0.f) };
            *reinterpret_cast<float2*>(C + (size_t)rg8 * 128 + col) = o;
        }
    }
}

// ---------------- fused pool + classifier head + log_softmax ------------------
__device__ __forceinline__ int lower_bound_batch(const void* batch, int N, int val) {
    int lo = 0, hi = N;
    while (lo < hi) {
        int mid = (lo + hi) >> 1;
        if (load_idx(batch, mid) < val) lo = mid + 1; else hi = mid;
    }
    return lo;
}

__global__ void head_kernel(const float* __restrict__ h, const void* __restrict__ batch,
                            int N,
                            const float* __restrict__ Wl1, const float* __restrict__ bl1,
                            const float* __restrict__ Wl2, const float* __restrict__ bl2,
                            float* __restrict__ out) {
    __shared__ float row[128];
    __shared__ float hid[128];
    __shared__ float lg[10];
    __shared__ float red[2];
    int gi = blockIdx.x;
    int t = threadIdx.x;

    int s = lower_bound_batch(batch, N, gi);
    int e = lower_bound_batch(batch, N, gi + 1);
    float sum = 0.f;
    for (int n = s; n < e; n++) sum += h[(size_t)n * 128 + t];
    row[t] = sum;
    __syncthreads();

    float v1 = bl1[t];
#pragma unroll 8
    for (int k = 0; k < 128; k++) v1 += row[k] * Wl1[k * 128 + t];
    hid[t] = fmaxf(v1, 0.f);
    __syncthreads();

    if (t < 10) {
        float v = bl2[t];
#pragma unroll 8
        for (int k = 0; k < 128; k++) v += hid[k] * Wl2[k * 10 + t];
        lg[t] = v;
    }
    __syncthreads();

    if (t == 0) {
        float m = lg[0];
        for (int i = 1; i < 10; i++) m = fmaxf(m, lg[i]);
        float se = 0.f;
        for (int i = 0; i < 10; i++) se += expf(lg[i] - m);
        red[0] = m;
        red[1] = logf(se);
    }
    __syncthreads();

    if (t < 10) out[(size_t)gi * 10 + t] = lg[t] - red[0] - red[1];
}

// ---------------- launch ------------------------------------------------------
extern "C" void kernel_launch(void* const* d_in, const int* in_sizes, int n_in,
                              void* d_out, int out_size) {
    const float* x     = (const float*)d_in[0];
    const void*  ei    = d_in[1];
    const void*  batch = d_in[2];
    const float* W1a = (const float*)d_in[3];
    const float* b1a = (const float*)d_in[4];
    const float* W1b = (const float*)d_in[5];
    const float* b1b = (const float*)d_in[6];
    const float* W2a = (const float*)d_in[7];
    const float* b2a = (const float*)d_in[8];
    const float* W2b = (const float*)d_in[9];
    const float* b2b = (const float*)d_in[10];
    const float* Wl1 = (const float*)d_in[11];
    const float* bl1 = (const float*)d_in[12];
    const float* Wl2 = (const float*)d_in[13];
    const float* bl2 = (const float*)d_in[14];
    float* out = (float*)d_out;

    const int N = in_sizes[0] / 128;
    const int E = in_sizes[1] / 2;

    float *agg, *hb, *wf;
    int *deg, *rowptr, *cursor, *csr, *bsum, *boff;
    cudaGetSymbolAddress((void**)&agg,    g_agg);
    cudaGetSymbolAddress((void**)&hb,     g_h);
    cudaGetSymbolAddress((void**)&deg,    g_deg);
    cudaGetSymbolAddress((void**)&rowptr, g_rowptr);
    cudaGetSymbolAddress((void**)&cursor, g_cursor);
    cudaGetSymbolAddress((void**)&csr,    g_csr);
    cudaGetSymbolAddress((void**)&bsum,   g_bsum);
    cudaGetSymbolAddress((void**)&boff,   g_boff);
    cudaGetSymbolAddress((void**)&wf,     g_wf);

    static bool smem_set = false;
    if (!smem_set) {
        cudaFuncSetAttribute(mlp_fused_kernel,
                             cudaFuncAttributeMaxDynamicSharedMemorySize,
                             MLP_SMEM_FLOATS * 4);
        smem_set = true;
    }

    const int edgeBlks   = (E + 255) / 256;
    const int gatherBlks = (N * 32 + 255) / 256;
    const int gemmBlks   = (N + 127) / 128;
    const int CH         = (N + 127) / 128;

    detect_kernel<<<1, 256>>>((const unsigned int*)ei, (long long)in_sizes[1]);

    wtransform_kernel<<<64, 256>>>(W1a, wf + 0 * 16384);
    wtransform_kernel<<<64, 256>>>(W1b, wf + 1 * 16384);
    wtransform_kernel<<<64, 256>>>(W2a, wf + 2 * 16384);
    wtransform_kernel<<<64, 256>>>(W2b, wf + 3 * 16384);

    // ---- CSR build ----
    zero_int_kernel<<<(N + 1 + 255) / 256, 256>>>(deg, N + 1);
    hist_kernel<<<edgeBlks, 256>>>(ei, E, deg);
    scan_partial_kernel<<<128, 256>>>(deg, N, CH, bsum);
    scan_bsum_kernel<<<1, 128>>>(bsum, boff, rowptr, N);
    scan_write_kernel<<<128, 256>>>(deg, N, CH, boff, rowptr, cursor);
    fill_kernel<<<edgeBlks, 256>>>(ei, E, cursor, csr);

    // ---- layer 1 ----
    gather_kernel<<<gatherBlks, 256>>>(x, csr, rowptr, N, agg);
    mlp_fused_kernel<<<gemmBlks, 256, MLP_SMEM_FLOATS * 4>>>(
        agg, wf + 0 * 16384, wf + 1 * 16384, b1a, b1b, hb, N);

    // ---- layer 2 ----
    gather_kernel<<<gatherBlks, 256>>>(hb, csr, rowptr, N, agg);
    mlp_fused_kernel<<<gemmBlks, 256, MLP_SMEM_FLOATS * 4>>>(
        agg, wf + 2 * 16384, wf + 3 * 16384, b2a, b2b, hb, N);

    // ---- fused pool + head ----
    head_kernel<<<1024, 128>>>(hb, batch, N, Wl1, bl1, Wl2, bl2, out);
}